// round 1
// baseline (speedup 1.0000x reference)
#include <cuda_runtime.h>
#include <math.h>

#define NROWS 4096
#define DIM   1024
#define TEMPF 0.05f
#define EPSF  1e-8f

// -------- device scratch (no runtime allocation allowed) --------
__device__ float g_cn [NROWS * DIM];
__device__ float g_chn[NROWS * DIM];
__device__ float g_row_val[NROWS];

// ============================================================
// Kernel 1: row-normalize c -> g_cn  and ch -> g_chn
// one block per row (2*NROWS blocks), 256 threads, DIM/4 = 256 float4
// ============================================================
__global__ __launch_bounds__(256)
void normalize_kernel(const float* __restrict__ c, const float* __restrict__ ch) {
    int row = blockIdx.x;
    const float* src = (row < NROWS) ? c : ch;
    float*       dst = (row < NROWS) ? g_cn : g_chn;
    int r = (row < NROWS) ? row : row - NROWS;

    const float4* srow = (const float4*)(src + (size_t)r * DIM);
    float4*       drow = (float4*)(dst + (size_t)r * DIM);

    int t = threadIdx.x;
    float4 v = srow[t];
    float ssq = v.x * v.x + v.y * v.y + v.z * v.z + v.w * v.w;

    #pragma unroll
    for (int o = 16; o > 0; o >>= 1)
        ssq += __shfl_xor_sync(0xffffffffu, ssq, o);

    __shared__ float wsum[8];
    if ((t & 31) == 0) wsum[t >> 5] = ssq;
    __syncthreads();

    float tot = 0.f;
    #pragma unroll
    for (int w = 0; w < 8; w++) tot += wsum[w];

    float rinv = 1.0f / fmaxf(sqrtf(tot), EPSF);
    drow[t] = make_float4(v.x * rinv, v.y * rinv, v.z * rinv, v.w * rinv);
}

// ============================================================
// Kernel 2: SGEMM  dot[i][j] = cn_i . chn_j   (both K-major, K=1024)
// 128x128 block tile, 256 threads, 8x8 per-thread microtile, BK=8
// ============================================================
#define BM 128
#define BN 128
#define BK 8
#define TM 8
#define TN 8

__global__ __launch_bounds__(256)
void gemm_kernel(float* __restrict__ out) {
    __shared__ float As[BK][BM];
    __shared__ float Bs[BK][BN];

    const int bx = blockIdx.x;           // column tile (j)
    const int by = blockIdx.y;           // row tile (i)
    const int t  = threadIdx.x;
    const int tx = t % 16;
    const int ty = t / 16;

    const float* A = g_cn  + (size_t)by * BM * DIM;
    const float* B = g_chn + (size_t)bx * BN * DIM;

    const int lr = t >> 1;               // 0..127 row within tile
    const int lk = (t & 1) * 4;          // 0 or 4

    float acc[TM][TN];
    #pragma unroll
    for (int m = 0; m < TM; m++)
        #pragma unroll
        for (int n = 0; n < TN; n++) acc[m][n] = 0.f;

    for (int k0 = 0; k0 < DIM; k0 += BK) {
        float4 a = *(const float4*)(A + (size_t)lr * DIM + k0 + lk);
        float4 b = *(const float4*)(B + (size_t)lr * DIM + k0 + lk);
        As[lk + 0][lr] = a.x; As[lk + 1][lr] = a.y;
        As[lk + 2][lr] = a.z; As[lk + 3][lr] = a.w;
        Bs[lk + 0][lr] = b.x; Bs[lk + 1][lr] = b.y;
        Bs[lk + 2][lr] = b.z; Bs[lk + 3][lr] = b.w;
        __syncthreads();

        #pragma unroll
        for (int k = 0; k < BK; k++) {
            float af[TM], bf[TN];
            *(float4*)(af)     = *(const float4*)&As[k][ty * TM];
            *(float4*)(af + 4) = *(const float4*)&As[k][ty * TM + 4];
            *(float4*)(bf)     = *(const float4*)&Bs[k][tx * TN];
            *(float4*)(bf + 4) = *(const float4*)&Bs[k][tx * TN + 4];
            #pragma unroll
            for (int m = 0; m < TM; m++)
                #pragma unroll
                for (int n = 0; n < TN; n++)
                    acc[m][n] += af[m] * bf[n];
        }
        __syncthreads();
    }

    // write out dot values (== sim * TEMP)
    #pragma unroll
    for (int m = 0; m < TM; m++) {
        float* crow = out + ((size_t)(by * BM + ty * TM + m)) * NROWS
                          + bx * BN + tx * TN;
        *(float4*)(crow)     = make_float4(acc[m][0], acc[m][1], acc[m][2], acc[m][3]);
        *(float4*)(crow + 4) = make_float4(acc[m][4], acc[m][5], acc[m][6], acc[m][7]);
    }
}

// ============================================================
// Kernel 3: per-row softmax stats + y_true write
// one block per row i, 256 threads
// ============================================================
__global__ __launch_bounds__(256)
void row_reduce_kernel(const float* __restrict__ sim_dot,
                       const int*   __restrict__ labels,
                       float*       __restrict__ y_out) {
    __shared__ float s[NROWS];          // full row of sim (logits), 16 KB
    __shared__ int   slab[NROWS];       // labels, 16 KB
    __shared__ float red[8];

    const int i = blockIdx.x;
    const int t = threadIdx.x;
    const int li = labels[i];

    // pass 0: stage row (scaled by 1/TEMP) + labels, local max
    float mx = -INFINITY;
    for (int j = t; j < NROWS; j += 256) {
        float v = sim_dot[(size_t)i * NROWS + j] / TEMPF;
        s[j] = v;
        slab[j] = labels[j];
        mx = fmaxf(mx, v);
    }
    // block max
    #pragma unroll
    for (int o = 16; o > 0; o >>= 1)
        mx = fmaxf(mx, __shfl_xor_sync(0xffffffffu, mx, o));
    if ((t & 31) == 0) red[t >> 5] = mx;
    __syncthreads();
    mx = red[0];
    #pragma unroll
    for (int w = 1; w < 8; w++) mx = fmaxf(mx, red[w]);
    __syncthreads();

    // pass 1: sumexp + masked sums + y_true
    float sum_e = 0.f, sum_l = 0.f, cnt = 0.f;
    for (int j = t; j < NROWS; j += 256) {
        float v = s[j] - mx;
        sum_e += expf(v);
        int eq = (slab[j] == li);
        y_out[(size_t)i * NROWS + j] = eq ? 1.0f : 0.0f;
        if (eq) { sum_l += v; cnt += 1.0f; }
    }

    // block sums (3 values)
    #pragma unroll
    for (int o = 16; o > 0; o >>= 1) {
        sum_e += __shfl_xor_sync(0xffffffffu, sum_e, o);
        sum_l += __shfl_xor_sync(0xffffffffu, sum_l, o);
        cnt   += __shfl_xor_sync(0xffffffffu, cnt,   o);
    }
    __shared__ float r_e[8], r_l[8], r_c[8];
    if ((t & 31) == 0) { r_e[t >> 5] = sum_e; r_l[t >> 5] = sum_l; r_c[t >> 5] = cnt; }
    __syncthreads();
    if (t == 0) {
        float te = 0.f, tl = 0.f, tc = 0.f;
        #pragma unroll
        for (int w = 0; w < 8; w++) { te += r_e[w]; tl += r_l[w]; tc += r_c[w]; }
        g_row_val[i] = tl / tc - logf(te);
    }
}

// ============================================================
// Kernel 4: loss = -mean(row_val)
// ============================================================
__global__ __launch_bounds__(256)
void loss_kernel(float* __restrict__ out_loss) {
    const int t = threadIdx.x;
    float sum = 0.f;
    for (int j = t; j < NROWS; j += 256) sum += g_row_val[j];
    #pragma unroll
    for (int o = 16; o > 0; o >>= 1)
        sum += __shfl_xor_sync(0xffffffffu, sum, o);
    __shared__ float red[8];
    if ((t & 31) == 0) red[t >> 5] = sum;
    __syncthreads();
    if (t == 0) {
        float tot = 0.f;
        #pragma unroll
        for (int w = 0; w < 8; w++) tot += red[w];
        out_loss[0] = -(tot / (float)NROWS);
    }
}

// ============================================================
// launch
// ============================================================
extern "C" void kernel_launch(void* const* d_in, const int* in_sizes, int n_in,
                              void* d_out, int out_size) {
    const float* c      = (const float*)d_in[0];
    const float* ch     = (const float*)d_in[1];
    const int*   labels = (const int*)d_in[2];

    float* out   = (float*)d_out;
    float* sim   = out;                                  // [N*N]
    float* loss  = out + (size_t)NROWS * NROWS;          // [1]
    float* ytrue = out + (size_t)NROWS * NROWS + 1;      // [N*N]

    normalize_kernel<<<2 * NROWS, 256>>>(c, ch);

    dim3 grid(NROWS / BN, NROWS / BM);
    gemm_kernel<<<grid, 256>>>(sim);

    row_reduce_kernel<<<NROWS, 256>>>(sim, labels, ytrue);

    loss_kernel<<<1, 256>>>(loss);
}

// round 3
// speedup vs baseline: 2.7282x; 2.7282x over previous
#include <cuda_runtime.h>
#include <cuda_bf16.h>
#include <math.h>
#include <stdint.h>

#define NROWS 4096
#define DIM   1024
#define TEMPF 0.05f
#define EPSF  1e-8f

// bf16x3 split-precision GEMM: K concatenated to 3*DIM
#define KTOT  3072
#define BM 128
#define BN 128
#define BK 64                       // bf16 per chunk = 128 bytes/row (SW128 atom)
#define NCHUNKS (KTOT / BK)         // 48
#define NSTAGES 3
#define A_STAGE_BYTES (BM * 128)    // 16 KB
#define B_STAGE_BYTES (BN * 128)    // 16 KB
#define STAGE_BYTES   (A_STAGE_BYTES + B_STAGE_BYTES)          // 32 KB
#define SMEM_DYN_BYTES (NSTAGES * STAGE_BYTES)                  // 96 KB

// -------- device scratch (no runtime allocation allowed) --------
__device__ __nv_bfloat16 g_a[(size_t)NROWS * KTOT];   // cn:  [hi | lo | hi]
__device__ __nv_bfloat16 g_b[(size_t)NROWS * KTOT];   // chn: [hi | hi | lo]
__device__ float g_row_val[NROWS];

// ============================================================
// helpers
// ============================================================
__device__ __forceinline__ uint32_t smem_u32(const void* p) {
    uint32_t a;
    asm("{ .reg .u64 t; cvta.to.shared.u64 t, %1; cvt.u32.u64 %0, t; }"
        : "=r"(a) : "l"(p));
    return a;
}

#define SW128(x) ((x) ^ (((x) >> 3) & 0x70))

__device__ __forceinline__ void cp_async16(uint32_t dst, const void* src) {
    asm volatile("cp.async.cg.shared.global [%0], [%1], 16;\n" :: "r"(dst), "l"(src));
}

__device__ __forceinline__ void ldsm_x4(uint32_t addr, uint32_t& r0, uint32_t& r1,
                                        uint32_t& r2, uint32_t& r3) {
    asm volatile("ldmatrix.sync.aligned.m8n8.x4.shared.b16 {%0,%1,%2,%3}, [%4];"
                 : "=r"(r0), "=r"(r1), "=r"(r2), "=r"(r3) : "r"(addr));
}

__device__ __forceinline__ void mma16816(float& c0, float& c1, float& c2, float& c3,
                                         uint32_t a0, uint32_t a1, uint32_t a2, uint32_t a3,
                                         uint32_t b0, uint32_t b1) {
    asm volatile(
        "mma.sync.aligned.m16n8k16.row.col.f32.bf16.bf16.f32 "
        "{%0,%1,%2,%3}, {%4,%5,%6,%7}, {%8,%9}, {%0,%1,%2,%3};"
        : "+f"(c0), "+f"(c1), "+f"(c2), "+f"(c3)
        : "r"(a0), "r"(a1), "r"(a2), "r"(a3), "r"(b0), "r"(b1));
}

// ============================================================
// Kernel 1: row-normalize + bf16 hi/lo split into g_a / g_b
// ============================================================
__global__ __launch_bounds__(256)
void normalize_split_kernel(const float* __restrict__ c, const float* __restrict__ ch) {
    int row = blockIdx.x;
    bool isC = (row < NROWS);
    int r = isC ? row : row - NROWS;
    const float4* srow = (const float4*)((isC ? c : ch) + (size_t)r * DIM);

    int t = threadIdx.x;
    float4 v = srow[t];
    float ssq = v.x * v.x + v.y * v.y + v.z * v.z + v.w * v.w;

    #pragma unroll
    for (int o = 16; o > 0; o >>= 1)
        ssq += __shfl_xor_sync(0xffffffffu, ssq, o);

    __shared__ float wsum[8];
    if ((t & 31) == 0) wsum[t >> 5] = ssq;
    __syncthreads();
    float tot = 0.f;
    #pragma unroll
    for (int w = 0; w < 8; w++) tot += wsum[w];

    float rinv = 1.0f / fmaxf(sqrtf(tot), EPSF);
    float x[4] = { v.x * rinv, v.y * rinv, v.z * rinv, v.w * rinv };

    union { __nv_bfloat16 h[4]; uint2 u; } phi, plo;
    #pragma unroll
    for (int i = 0; i < 4; i++) {
        phi.h[i] = __float2bfloat16(x[i]);
        plo.h[i] = __float2bfloat16(x[i] - __bfloat162float(phi.h[i]));
    }

    __nv_bfloat16* dst = (isC ? g_a : g_b) + (size_t)r * KTOT + t * 4;
    if (isC) {
        *(uint2*)(dst)            = phi.u;   // hi
        *(uint2*)(dst + DIM)      = plo.u;   // lo
        *(uint2*)(dst + 2 * DIM)  = phi.u;   // hi
    } else {
        *(uint2*)(dst)            = phi.u;   // hi
        *(uint2*)(dst + DIM)      = phi.u;   // hi
        *(uint2*)(dst + 2 * DIM)  = plo.u;   // lo
    }
}

// ============================================================
// Kernel 2: mma.sync bf16 GEMM, 128x128 tile, K=3072
// 8 warps as 4(M) x 2(N); warp tile 32x64; mma m16n8k16
// ============================================================
__device__ __forceinline__ void load_chunk(const __nv_bfloat16* gA, const __nv_bfloat16* gB,
                                           int kc, uint32_t sA, uint32_t sB, int t) {
    int ke = kc * BK;
    #pragma unroll
    for (int i = 0; i < 4; i++) {                   // A: 128 rows * 8 blocks / 256 thr
        int idx = i * 256 + t;
        int r = idx >> 3, cb = idx & 7;
        cp_async16(sA + SW128(r * 128 + cb * 16), gA + (size_t)r * KTOT + ke + cb * 8);
    }
    #pragma unroll
    for (int i = 0; i < 4; i++) {                   // B: same shape
        int idx = i * 256 + t;
        int r = idx >> 3, cb = idx & 7;
        cp_async16(sB + SW128(r * 128 + cb * 16), gB + (size_t)r * KTOT + ke + cb * 8);
    }
    asm volatile("cp.async.commit_group;\n" ::: "memory");
}

__global__ __launch_bounds__(256)
void gemm_kernel(float* __restrict__ out) {
    extern __shared__ char dyn_smem[];

    const int t    = threadIdx.x;
    const int wid  = t >> 5;
    const int lane = t & 31;
    const int wm   = wid >> 1;          // 0..3  (M warp)
    const int wn   = wid & 1;           // 0..1  (N warp)
    const int bx   = blockIdx.x;        // N tile
    const int by   = blockIdx.y;        // M tile

    uint32_t smem = smem_u32(dyn_smem);

    const __nv_bfloat16* gA = g_a + (size_t)by * BM * KTOT;
    const __nv_bfloat16* gB = g_b + (size_t)bx * BN * KTOT;

    float acc[2][8][4];
    #pragma unroll
    for (int mi = 0; mi < 2; mi++)
        #pragma unroll
        for (int ni = 0; ni < 8; ni++)
            #pragma unroll
            for (int q = 0; q < 4; q++) acc[mi][ni][q] = 0.f;

    // prologue: 2 chunks in flight
    load_chunk(gA, gB, 0, smem, smem + A_STAGE_BYTES, t);
    load_chunk(gA, gB, 1, smem + STAGE_BYTES, smem + STAGE_BYTES + A_STAGE_BYTES, t);

    // per-thread ldmatrix address components (within-tile, before swizzle)
    const int a_row_in16 = lane & 15;            // row within m16 tile
    const int a_kadd     = ((lane >> 4) & 1) * 16;   // +16B for k8..15 halves
    const int b_row_in16 = (lane & 7) + (((lane >> 4) & 1) << 3); // n row within n16 group
    const int b_kadd     = ((lane >> 3) & 1) * 16;

    for (int kc = 0; kc < NCHUNKS; kc++) {
        // keep pipeline full (empty commit in tail keeps wait_group math uniform)
        if (kc + 2 < NCHUNKS) {
            int s = (kc + 2) % NSTAGES;
            load_chunk(gA, gB, kc + 2, smem + s * STAGE_BYTES,
                       smem + s * STAGE_BYTES + A_STAGE_BYTES, t);
        } else {
            asm volatile("cp.async.commit_group;\n" ::: "memory");
        }

        asm volatile("cp.async.wait_group 2;\n" ::: "memory");
        __syncthreads();

        uint32_t sA = smem + (kc % NSTAGES) * STAGE_BYTES;
        uint32_t sB = sA + A_STAGE_BYTES;

        #pragma unroll
        for (int ks = 0; ks < 4; ks++) {         // 4 x k16 within the 64-elem chunk
            const int kb = ks * 32;              // byte offset of this k16 in the row

            uint32_t af[2][4];
            #pragma unroll
            for (int mi = 0; mi < 2; mi++) {
                int row = wm * 32 + mi * 16 + a_row_in16;
                uint32_t addr = sA + SW128(row * 128 + kb + a_kadd);
                ldsm_x4(addr, af[mi][0], af[mi][1], af[mi][2], af[mi][3]);
            }

            uint32_t bf[4][4];                   // [n16 group][b0t0,b1t0,b0t1,b1t1]
            #pragma unroll
            for (int nj = 0; nj < 4; nj++) {
                int row = wn * 64 + nj * 16 + b_row_in16;
                uint32_t addr = sB + SW128(row * 128 + kb + b_kadd);
                ldsm_x4(addr, bf[nj][0], bf[nj][1], bf[nj][2], bf[nj][3]);
            }

            #pragma unroll
            for (int mi = 0; mi < 2; mi++)
                #pragma unroll
                for (int nj = 0; nj < 4; nj++) {
                    mma16816(acc[mi][nj * 2 + 0][0], acc[mi][nj * 2 + 0][1],
                             acc[mi][nj * 2 + 0][2], acc[mi][nj * 2 + 0][3],
                             af[mi][0], af[mi][1], af[mi][2], af[mi][3],
                             bf[nj][0], bf[nj][1]);
                    mma16816(acc[mi][nj * 2 + 1][0], acc[mi][nj * 2 + 1][1],
                             acc[mi][nj * 2 + 1][2], acc[mi][nj * 2 + 1][3],
                             af[mi][0], af[mi][1], af[mi][2], af[mi][3],
                             bf[nj][2], bf[nj][3]);
                }
        }
        __syncthreads();   // stage consumed; safe to overwrite next iteration
    }

    // epilogue: direct register stores
    const int r0 = by * BM + wm * 32 + (lane >> 2);
    const int c0 = bx * BN + wn * 64 + (lane & 3) * 2;
    #pragma unroll
    for (int mi = 0; mi < 2; mi++)
        #pragma unroll
        for (int ni = 0; ni < 8; ni++) {
            float* p = out + (size_t)(r0 + mi * 16) * NROWS + c0 + ni * 8;
            *(float2*)(p)                      = make_float2(acc[mi][ni][0], acc[mi][ni][1]);
            *(float2*)(p + (size_t)8 * NROWS)  = make_float2(acc[mi][ni][2], acc[mi][ni][3]);
        }
}

// ============================================================
// Kernel 3: per-row softmax stats + y_true write
// ============================================================
__global__ __launch_bounds__(256)
void row_reduce_kernel(const float* __restrict__ sim_dot,
                       const int*   __restrict__ labels,
                       float*       __restrict__ y_out) {
    __shared__ float s[NROWS];
    __shared__ int   slab[NROWS];
    __shared__ float red[8];

    const int i = blockIdx.x;
    const int t = threadIdx.x;
    const int li = labels[i];

    float mx = -INFINITY;
    for (int j = t; j < NROWS; j += 256) {
        float v = sim_dot[(size_t)i * NROWS + j] / TEMPF;
        s[j] = v;
        slab[j] = labels[j];
        mx = fmaxf(mx, v);
    }
    #pragma unroll
    for (int o = 16; o > 0; o >>= 1)
        mx = fmaxf(mx, __shfl_xor_sync(0xffffffffu, mx, o));
    if ((t & 31) == 0) red[t >> 5] = mx;
    __syncthreads();
    mx = red[0];
    #pragma unroll
    for (int w = 1; w < 8; w++) mx = fmaxf(mx, red[w]);
    __syncthreads();

    float sum_e = 0.f, sum_l = 0.f, cnt = 0.f;
    for (int j = t; j < NROWS; j += 256) {
        float v = s[j] - mx;
        sum_e += expf(v);
        int eq = (slab[j] == li);
        y_out[(size_t)i * NROWS + j] = eq ? 1.0f : 0.0f;
        if (eq) { sum_l += v; cnt += 1.0f; }
    }
    #pragma unroll
    for (int o = 16; o > 0; o >>= 1) {
        sum_e += __shfl_xor_sync(0xffffffffu, sum_e, o);
        sum_l += __shfl_xor_sync(0xffffffffu, sum_l, o);
        cnt   += __shfl_xor_sync(0xffffffffu, cnt,   o);
    }
    __shared__ float r_e[8], r_l[8], r_c[8];
    if ((t & 31) == 0) { r_e[t >> 5] = sum_e; r_l[t >> 5] = sum_l; r_c[t >> 5] = cnt; }
    __syncthreads();
    if (t == 0) {
        float te = 0.f, tl = 0.f, tc = 0.f;
        #pragma unroll
        for (int w = 0; w < 8; w++) { te += r_e[w]; tl += r_l[w]; tc += r_c[w]; }
        g_row_val[i] = tl / tc - logf(te);
    }
}

// ============================================================
// Kernel 4: loss = -mean(row_val)
// ============================================================
__global__ __launch_bounds__(256)
void loss_kernel(float* __restrict__ out_loss) {
    const int t = threadIdx.x;
    float sum = 0.f;
    for (int j = t; j < NROWS; j += 256) sum += g_row_val[j];
    #pragma unroll
    for (int o = 16; o > 0; o >>= 1)
        sum += __shfl_xor_sync(0xffffffffu, sum, o);
    __shared__ float red[8];
    if ((t & 31) == 0) red[t >> 5] = sum;
    __syncthreads();
    if (t == 0) {
        float tot = 0.f;
        #pragma unroll
        for (int w = 0; w < 8; w++) tot += red[w];
        out_loss[0] = -(tot / (float)NROWS);
    }
}

// ============================================================
// launch
// ============================================================
extern "C" void kernel_launch(void* const* d_in, const int* in_sizes, int n_in,
                              void* d_out, int out_size) {
    const float* c      = (const float*)d_in[0];
    const float* ch     = (const float*)d_in[1];
    const int*   labels = (const int*)d_in[2];

    float* out   = (float*)d_out;
    float* sim   = out;
    float* loss  = out + (size_t)NROWS * NROWS;
    float* ytrue = out + (size_t)NROWS * NROWS + 1;

    normalize_split_kernel<<<2 * NROWS, 256>>>(c, ch);

    cudaFuncSetAttribute(gemm_kernel, cudaFuncAttributeMaxDynamicSharedMemorySize,
                         SMEM_DYN_BYTES);
    dim3 grid(NROWS / BN, NROWS / BM);
    gemm_kernel<<<grid, 256, SMEM_DYN_BYTES>>>(sim);

    row_reduce_kernel<<<NROWS, 256>>>(sim, labels, ytrue);

    loss_kernel<<<1, 256>>>(loss);
}